// round 2
// baseline (speedup 1.0000x reference)
#include <cuda_runtime.h>

// Problem dims
#define NE   8
#define NB   16384
#define ND   1024
#define NHH  512
#define NGH  128

// ---------------- device scratch (no allocs allowed) ----------------
__device__ __align__(16) float g_tmp[(size_t)NE * NHH * NHH];     // Wvm@Wo      8 MB
__device__ __align__(16) float g_Wc[(size_t)NE * ND * NHH];       // Wv@(Wvm@Wo) 16 MB
__device__ __align__(16) float g_bc[NE * NHH];                    // combined bias
__device__ __align__(16) float g_hidden[(size_t)NB * NGH];        // gate hidden 8 MB
__device__ __align__(16) float g_gate[NB * NE];                   // softmax gate

// ---------------- generic 64x64x16 tiled GEMM (batched over z) ----------------
// C[z] = A[z] @ B[z]  (+ bias, optional relu). Row-major. M,N,K multiples of 64/64/16.
__global__ __launch_bounds__(256) void gemm64(
    const float* __restrict__ A, const float* __restrict__ Bm, float* __restrict__ C,
    int M, int N, int K, long sA, long sB, long sC,
    const float* __restrict__ bias, int relu)
{
    __shared__ float As[16][64];
    __shared__ float Bs[16][64];

    int z = blockIdx.z;
    A  += (long)z * sA;
    Bm += (long)z * sB;
    C  += (long)z * sC;

    int tid = threadIdx.x;
    int bm = blockIdx.y * 64;
    int bn = blockIdx.x * 64;
    int tx = tid & 15, ty = tid >> 4;

    float acc[4][4] = {};

    int ra = tid >> 2, ca = (tid & 3) * 4;   // A: 64 rows x 16 cols
    int rb = tid >> 4, cb = (tid & 15) * 4;  // B: 16 rows x 64 cols

    for (int k0 = 0; k0 < K; k0 += 16) {
        float4 va = *(const float4*)(A + (size_t)(bm + ra) * K + k0 + ca);
        As[ca + 0][ra] = va.x;
        As[ca + 1][ra] = va.y;
        As[ca + 2][ra] = va.z;
        As[ca + 3][ra] = va.w;
        *(float4*)&Bs[rb][cb] = *(const float4*)(Bm + (size_t)(k0 + rb) * N + bn + cb);
        __syncthreads();
#pragma unroll
        for (int k = 0; k < 16; k++) {
            float a[4], b[4];
            *(float4*)&a[0] = *(const float4*)&As[k][ty * 4];
            *(float4*)&b[0] = *(const float4*)&Bs[k][tx * 4];
#pragma unroll
            for (int i = 0; i < 4; i++)
#pragma unroll
                for (int j = 0; j < 4; j++)
                    acc[i][j] += a[i] * b[j];
        }
        __syncthreads();
    }

#pragma unroll
    for (int i = 0; i < 4; i++) {
        int r = bm + ty * 4 + i;
#pragma unroll
        for (int j = 0; j < 4; j++) {
            int c = bn + tx * 4 + j;
            float v = acc[i][j];
            if (bias) v += bias[c];
            if (relu) v = fmaxf(v, 0.0f);
            C[(size_t)r * N + c] = v;
        }
    }
}

// ---------------- combined bias: bc = bv@tmp + bvm@Wo + bo ----------------
__global__ __launch_bounds__(256) void bias_kernel(
    const float* __restrict__ bv, const float* __restrict__ bvm,
    const float* __restrict__ bo, const float* __restrict__ Wo,
    const float* __restrict__ tmp, float* __restrict__ bc)
{
    int e = blockIdx.y;
    int h = blockIdx.x * 256 + threadIdx.x;
    const float* WoE  = Wo  + (size_t)e * NHH * NHH;
    const float* tmpE = tmp + (size_t)e * NHH * NHH;
    float s = bo[e * NHH + h];
    for (int g = 0; g < NHH; g++) {
        s += bvm[e * NHH + g] * WoE[(size_t)g * NHH + h];
        s += bv[e * NHH + g]  * tmpE[(size_t)g * NHH + h];
    }
    bc[e * NHH + h] = s;
}

// ---------------- gate logits + softmax ----------------
__global__ __launch_bounds__(256) void gate_kernel(
    const float* __restrict__ hidden, const float* __restrict__ Wg2,
    const float* __restrict__ bg2, float* __restrict__ gate)
{
    int b = blockIdx.x * blockDim.x + threadIdx.x;
    float l[NE];
#pragma unroll
    for (int ee = 0; ee < NE; ee++) l[ee] = bg2[ee];
    const float* h = hidden + (size_t)b * NGH;
    for (int g = 0; g < NGH; g++) {
        float hv = h[g];
#pragma unroll
        for (int ee = 0; ee < NE; ee++) l[ee] += hv * Wg2[g * NE + ee];
    }
    float m = l[0];
#pragma unroll
    for (int ee = 1; ee < NE; ee++) m = fmaxf(m, l[ee]);
    float sum = 0.0f;
#pragma unroll
    for (int ee = 0; ee < NE; ee++) { l[ee] = __expf(l[ee] - m); sum += l[ee]; }
    float inv = 1.0f / sum;
#pragma unroll
    for (int ee = 0; ee < NE; ee++) gate[b * NE + ee] = l[ee] * inv;
}

// ---------------- main fused kernel ----------------
// out[b,h] = sum_e gate[b,e] * (freq[e,b,:] @ Wc[e])[h] + sum_e gate[b,e]*bc[e,h]
// 128x128 tile, BK=16, 256 threads, 8x8 microtile. Gate folded into the A smem load.
__global__ __launch_bounds__(256) void fused_main(
    const float* __restrict__ freq, const float* __restrict__ Wc,
    const float* __restrict__ gate, const float* __restrict__ bc,
    float* __restrict__ out)
{
    __shared__ float As[16][128];
    __shared__ float Bs[16][128];
    __shared__ float sg[128];

    int tid = threadIdx.x;
    int bm = blockIdx.y * 128;
    int bn = blockIdx.x * 128;
    int tx = tid & 15, ty = tid >> 4;

    float acc[8][8];
#pragma unroll
    for (int i = 0; i < 8; i++)
#pragma unroll
        for (int j = 0; j < 8; j++) acc[i][j] = 0.0f;

    for (int e = 0; e < NE; e++) {
        if (tid < 128) sg[tid] = gate[(size_t)(bm + tid) * NE + e];
        __syncthreads();
        const float* Ae = freq + ((size_t)e * NB + bm) * ND;
        const float* Be = Wc + (size_t)e * ND * NHH;

        for (int k0 = 0; k0 < ND; k0 += 16) {
            // A tile: 128x16, gate-scaled, stored transposed
#pragma unroll
            for (int p = 0; p < 2; p++) {
                int r = (tid >> 2) + p * 64;
                int c = (tid & 3) * 4;
                float4 v = *(const float4*)(Ae + (size_t)r * ND + k0 + c);
                float s = sg[r];
                As[c + 0][r] = v.x * s;
                As[c + 1][r] = v.y * s;
                As[c + 2][r] = v.z * s;
                As[c + 3][r] = v.w * s;
            }
            // B tile: 16x128
#pragma unroll
            for (int p = 0; p < 2; p++) {
                int r = (tid >> 5) + p * 8;
                int c = (tid & 31) * 4;
                *(float4*)&Bs[r][c] = *(const float4*)(Be + (size_t)(k0 + r) * NHH + bn + c);
            }
            __syncthreads();
#pragma unroll
            for (int k = 0; k < 16; k++) {
                float a[8], b[8];
                *(float4*)&a[0] = *(const float4*)&As[k][ty * 4];
                *(float4*)&a[4] = *(const float4*)&As[k][64 + ty * 4];
                *(float4*)&b[0] = *(const float4*)&Bs[k][tx * 4];
                *(float4*)&b[4] = *(const float4*)&Bs[k][64 + tx * 4];
#pragma unroll
                for (int i = 0; i < 8; i++)
#pragma unroll
                    for (int j = 0; j < 8; j++)
                        acc[i][j] += a[i] * b[j];
            }
            __syncthreads();
        }
    }

    // row/col indices of this thread's 8x8 microtile
    int rows[8], cols[8];
#pragma unroll
    for (int i = 0; i < 4; i++) {
        rows[i]     = bm + ty * 4 + i;
        rows[i + 4] = bm + 64 + ty * 4 + i;
        cols[i]     = bn + tx * 4 + i;
        cols[i + 4] = bn + 64 + tx * 4 + i;
    }

    // bias epilogue: + sum_e gate[b,e] * bc[e,h]
#pragma unroll
    for (int e = 0; e < NE; e++) {
        float gr[8], bv8[8];
#pragma unroll
        for (int i = 0; i < 8; i++) gr[i] = __ldg(&gate[(size_t)rows[i] * NE + e]);
#pragma unroll
        for (int j = 0; j < 8; j++) bv8[j] = __ldg(&bc[e * NHH + cols[j]]);
#pragma unroll
        for (int i = 0; i < 8; i++)
#pragma unroll
            for (int j = 0; j < 8; j++)
                acc[i][j] += gr[i] * bv8[j];
    }

#pragma unroll
    for (int i = 0; i < 8; i++) {
        float4 v0 = make_float4(acc[i][0], acc[i][1], acc[i][2], acc[i][3]);
        float4 v1 = make_float4(acc[i][4], acc[i][5], acc[i][6], acc[i][7]);
        *(float4*)(out + (size_t)rows[i] * NHH + cols[0]) = v0;
        *(float4*)(out + (size_t)rows[i] * NHH + cols[4]) = v1;
    }
}

// ---------------- launcher ----------------
extern "C" void kernel_launch(void* const* d_in, const int* in_sizes, int n_in,
                              void* d_out, int out_size)
{
    const float* freq = (const float*)d_in[0];   // (E,B,D)
    const float* sem  = (const float*)d_in[1];   // (B,D)
    // d_in[2..5] = Wq,bq,Wk,bk : dead code (softmax over 1 key is identity)
    const float* Wv   = (const float*)d_in[6];   // (E,D,H)
    const float* bv   = (const float*)d_in[7];   // (E,H)
    // d_in[8..11] = Wqm,bqm,Wkm,bkm : dead code
    const float* Wvm  = (const float*)d_in[12];  // (E,H,H)
    const float* bvm  = (const float*)d_in[13];  // (E,H)
    const float* Wo   = (const float*)d_in[14];  // (E,H,H)
    const float* bo   = (const float*)d_in[15];  // (E,H)
    const float* Wg1  = (const float*)d_in[16];  // (D,GH)
    const float* bg1  = (const float*)d_in[17];  // (GH)
    const float* Wg2  = (const float*)d_in[18];  // (GH,E)
    const float* bg2  = (const float*)d_in[19];  // (E)
    float* out = (float*)d_out;

    float *tmp, *Wc, *bc, *hidden, *gate;
    cudaGetSymbolAddress((void**)&tmp,    g_tmp);
    cudaGetSymbolAddress((void**)&Wc,     g_Wc);
    cudaGetSymbolAddress((void**)&bc,     g_bc);
    cudaGetSymbolAddress((void**)&hidden, g_hidden);
    cudaGetSymbolAddress((void**)&gate,   g_gate);

    // 1) tmp[e] = Wvm[e] @ Wo[e]                 (E x 512x512x512)
    gemm64<<<dim3(NHH / 64, NHH / 64, NE), 256>>>(
        Wvm, Wo, tmp, NHH, NHH, NHH,
        (long)NHH * NHH, (long)NHH * NHH, (long)NHH * NHH, nullptr, 0);

    // 2) bc[e] = bv@tmp + bvm@Wo + bo
    bias_kernel<<<dim3(NHH / 256, NE), 256>>>(bv, bvm, bo, Wo, tmp, bc);

    // 3) Wc[e] = Wv[e] @ tmp[e]                  (E x 1024x512x512)
    gemm64<<<dim3(NHH / 64, ND / 64, NE), 256>>>(
        Wv, tmp, Wc, ND, NHH, NHH,
        (long)ND * NHH, (long)NHH * NHH, (long)ND * NHH, nullptr, 0);

    // 4) hidden = relu(sem @ Wg1 + bg1)          (16384x1024x128)
    gemm64<<<dim3(NGH / 64, NB / 64, 1), 256>>>(
        sem, Wg1, hidden, NB, NGH, ND, 0, 0, 0, bg1, 1);

    // 5) gate = softmax(hidden @ Wg2 + bg2)
    gate_kernel<<<NB / 256, 256>>>(hidden, Wg2, bg2, gate);

    // 6) out[b,h] = sum_e gate[b,e]*(freq[e,b]@Wc[e])[h] + sum_e gate[b,e]*bc[e,h]
    fused_main<<<dim3(NHH / 128, NB / 128), 256>>>(freq, Wc, gate, bc, out);
}